// round 9
// baseline (speedup 1.0000x reference)
#include <cuda_runtime.h>
#include <cstdint>

#define V 12288
#define CIN 16
#define COUT 32
#define KORD 5
#define NKS 3               // k-slices per pass  -> 96*3 = 288 CTAs = 1 wave @2/SM
#define KSL (V / NKS)       // 4096
#define CHK 64              // u per chunk
#define NCHK (KSL / CHK)    // 64
#define CV (CIN * V)
#define RS 72               // smem row stride in bf16 elements
#define RSB (RS * 2)        // 144 bytes

// Scratch: reconstructed T1..T3 and per-pass k-slice partials
__device__ float g_T[3][CV];
__device__ float g_part[4][NKS][CV];

// per-stage smem byte offsets
#define AH_OFF 0
#define AL_OFF (128 * RSB)            // 18432
#define BH_OFF (2 * 128 * RSB)        // 36864
#define BL_OFF (BH_OFF + 16 * RSB)    // 39168
#define STAGE  (BL_OFF + 16 * RSB)    // 41472 per stage
#define SMEM_DYN (2 * STAGE)          // 82944

__device__ __forceinline__ uint32_t lds32(uint32_t a) {
    uint32_t v;
    asm volatile("ld.shared.b32 %0, [%1];" : "=r"(v) : "r"(a));
    return v;
}
__device__ __forceinline__ void sts64(uint32_t a, uint32_t w0, uint32_t w1) {
    asm volatile("st.shared.v2.b32 [%0], {%1,%2};" :: "r"(a), "r"(w0), "r"(w1) : "memory");
}

// split fp32 x4 -> bf16 hi (truncate) + bf16 lo (residual, RN); store 8B to each tile
__device__ __forceinline__ void split_sts(float4 f, uint32_t ah, uint32_t al) {
    uint32_t b0 = __float_as_uint(f.x), b1 = __float_as_uint(f.y);
    uint32_t b2 = __float_as_uint(f.z), b3 = __float_as_uint(f.w);
    uint32_t h0 = __byte_perm(b0, b1, 0x7632);
    uint32_t h1 = __byte_perm(b2, b3, 0x7632);
    float l0 = f.x - __uint_as_float(b0 & 0xFFFF0000u);
    float l1 = f.y - __uint_as_float(b1 & 0xFFFF0000u);
    float l2 = f.z - __uint_as_float(b2 & 0xFFFF0000u);
    float l3 = f.w - __uint_as_float(b3 & 0xFFFF0000u);
    uint32_t w0, w1;
    asm("cvt.rn.bf16x2.f32 %0, %1, %2;" : "=r"(w0) : "f"(l1), "f"(l0));
    asm("cvt.rn.bf16x2.f32 %0, %1, %2;" : "=r"(w1) : "f"(l3), "f"(l2));
    sts64(ah, h0, h1);
    sts64(al, w0, w1);
}

__device__ __forceinline__ void mma_bf16(float* c, uint32_t a0, uint32_t a1,
                                         uint32_t a2, uint32_t a3,
                                         uint32_t b0, uint32_t b1) {
    asm volatile("mma.sync.aligned.m16n8k16.row.col.f32.bf16.bf16.f32 "
                 "{%0,%1,%2,%3}, {%4,%5,%6,%7}, {%8,%9}, {%0,%1,%2,%3};"
                 : "+f"(c[0]), "+f"(c[1]), "+f"(c[2]), "+f"(c[3])
                 : "r"(a0), "r"(a1), "r"(a2), "r"(a3), "r"(b0), "r"(b1));
}

// B-stream bundle: MODE 0: B = s0
//                  MODE 1: B = s0+s1+s2                (T1 from pass-1 partials)
//                  MODE 2: B = 2*(s0+s1+s2) - sp       (recurrence fused)
struct BRegs { float4 b0, b1, b2, bp; };

template <int MODE>
__device__ __forceinline__ void load_b(BRegs& r,
                                       const float* s0, const float* s1,
                                       const float* s2, const float* sp, int off) {
    r.b0 = __ldg((const float4*)(s0 + off));
    if (MODE >= 1) {
        r.b1 = __ldg((const float4*)(s1 + off));
        r.b2 = __ldg((const float4*)(s2 + off));
    }
    if (MODE == 2) r.bp = __ldg((const float4*)(sp + off));
}
template <int MODE>
__device__ __forceinline__ float4 combine_b(const BRegs& r) {
    if (MODE == 0) return r.b0;
    float4 s;
    s.x = r.b0.x + r.b1.x + r.b2.x;
    s.y = r.b0.y + r.b1.y + r.b2.y;
    s.z = r.b0.z + r.b1.z + r.b2.z;
    s.w = r.b0.w + r.b1.w + r.b2.w;
    if (MODE == 2) {
        s.x = 2.0f * s.x - r.bp.x;
        s.y = 2.0f * s.y - r.bp.y;
        s.z = 2.0f * s.z - r.bp.z;
        s.w = 2.0f * s.w - r.bp.w;
    }
    return s;
}

// ---------------- pass kernel ----------------
// part[ks][ch][v] = sum_{u in kslice} B[ch][u] * L[v][u],  B reconstructed per MODE.
// vt==0 CTAs also write the reconstructed B (= T_{k-1}) to Tout.
template <int MODE>
__global__ __launch_bounds__(256, 2)
void cheb_pass_mma(const float* __restrict__ L,
                   const float* __restrict__ s0,
                   const float* __restrict__ s1,
                   const float* __restrict__ s2,
                   const float* __restrict__ sp,
                   float* __restrict__ Tout,
                   float* __restrict__ part)
{
    extern __shared__ __align__(16) uint8_t smem[];
    const uint32_t sb = (uint32_t)__cvta_generic_to_shared(smem);

    const int t    = threadIdx.x;
    const int warp = t >> 5;
    const int lane = t & 31;
    const int g    = lane >> 2;
    const int tc   = lane & 3;
    const int vt   = blockIdx.x % 96;
    const int ks   = blockIdx.x / 96;
    const int ub   = ks * KSL;

    // Coalesced staging map: thread t, iter j -> row j*16 + (t>>4), col quad (t&15).
    const int rh = t >> 4;
    const int cq = t & 15;
    const float* Ag = L + (size_t)(vt * 128 + rh) * V + ub + cq * 4;
    const int boff0 = rh * V + ub + cq * 4;      // offset into B streams
    const uint32_t st_off = (uint32_t)(rh * RSB + cq * 8);
    const bool wT = (Tout != nullptr) && (vt == 0);

    // fragment LDS offsets (relative to stage base)
    const int vw = warp * 16;
    const uint32_t a_frag = (uint32_t)((vw + g) * RSB + tc * 4);
    const uint32_t b_frag = (uint32_t)(g * RSB + tc * 4);

    float c0[4] = {0.f, 0.f, 0.f, 0.f};
    float c1[4] = {0.f, 0.f, 0.f, 0.f};

    float4 la[8];
    BRegs lb;

    // prologue: load+stage chunk 0, load chunk 1
#pragma unroll
    for (int j = 0; j < 8; j++)
        la[j] = __ldcs((const float4*)(Ag + (size_t)j * 16 * V));
    load_b<MODE>(lb, s0, s1, s2, sp, boff0);
    {
#pragma unroll
        for (int j = 0; j < 8; j++)
            split_sts(la[j], sb + AH_OFF + st_off + j * 2304,
                             sb + AL_OFF + st_off + j * 2304);
        float4 b4 = combine_b<MODE>(lb);
        split_sts(b4, sb + BH_OFF + st_off, sb + BL_OFF + st_off);
        if (wT) *(float4*)(Tout + boff0) = b4;
    }
#pragma unroll
    for (int j = 0; j < 8; j++)
        la[j] = __ldcs((const float4*)(Ag + (size_t)j * 16 * V + CHK));
    load_b<MODE>(lb, s0, s1, s2, sp, boff0 + CHK);
    __syncthreads();

#pragma unroll 1
    for (int c = 0; c < NCHK; c++) {
        const uint32_t sbuf = sb + (uint32_t)(c & 1) * STAGE;

        // stage chunk c+1 into the other buffer
        if (c + 1 < NCHK) {
            const uint32_t so = sb + (uint32_t)((c + 1) & 1) * STAGE;
#pragma unroll
            for (int j = 0; j < 8; j++)
                split_sts(la[j], so + AH_OFF + st_off + j * 2304,
                                 so + AL_OFF + st_off + j * 2304);
            float4 b4 = combine_b<MODE>(lb);
            split_sts(b4, so + BH_OFF + st_off, so + BL_OFF + st_off);
            if (wT) *(float4*)(Tout + boff0 + (c + 1) * CHK) = b4;
        }
        // prefetch chunk c+2
        if (c + 2 < NCHK) {
            const int off = (c + 2) * CHK;
#pragma unroll
            for (int j = 0; j < 8; j++)
                la[j] = __ldcs((const float4*)(Ag + (size_t)j * 16 * V + off));
            load_b<MODE>(lb, s0, s1, s2, sp, boff0 + off);
        }

        // compute chunk c: 4 k-steps x (2 n-tiles x 3 products)
#pragma unroll
        for (int s = 0; s < 4; s++) {
            const uint32_t ao = sbuf + a_frag + s * 32;
            const uint32_t bo = sbuf + b_frag + s * 32;
            uint32_t ah0 = lds32(ao + AH_OFF);
            uint32_t ah1 = lds32(ao + AH_OFF + 8 * RSB);
            uint32_t ah2 = lds32(ao + AH_OFF + 16);
            uint32_t ah3 = lds32(ao + AH_OFF + 8 * RSB + 16);
            uint32_t al0 = lds32(ao + AL_OFF);
            uint32_t al1 = lds32(ao + AL_OFF + 8 * RSB);
            uint32_t al2 = lds32(ao + AL_OFF + 16);
            uint32_t al3 = lds32(ao + AL_OFF + 8 * RSB + 16);

            uint32_t bh0 = lds32(bo + BH_OFF);
            uint32_t bh1 = lds32(bo + BH_OFF + 16);
            uint32_t bl0 = lds32(bo + BL_OFF);
            uint32_t bl1 = lds32(bo + BL_OFF + 16);
            mma_bf16(c0, ah0, ah1, ah2, ah3, bh0, bh1);
            mma_bf16(c0, ah0, ah1, ah2, ah3, bl0, bl1);
            mma_bf16(c0, al0, al1, al2, al3, bh0, bh1);

            uint32_t ch0 = lds32(bo + BH_OFF + 8 * RSB);
            uint32_t ch1 = lds32(bo + BH_OFF + 8 * RSB + 16);
            uint32_t cl0 = lds32(bo + BL_OFF + 8 * RSB);
            uint32_t cl1 = lds32(bo + BL_OFF + 8 * RSB + 16);
            mma_bf16(c1, ah0, ah1, ah2, ah3, ch0, ch1);
            mma_bf16(c1, ah0, ah1, ah2, ah3, cl0, cl1);
            mma_bf16(c1, al0, al1, al2, al3, ch0, ch1);
        }
        __syncthreads();
    }

    // epilogue: thread map rows g,g+8; cols 2tc,2tc+1
    {
        float* po = part + (size_t)ks * CV;
        const int v = vt * 128 + vw + g;
        const int cha = 2 * tc;
        const int chb = 8 + 2 * tc;
        po[(size_t)cha * V + v]           = c0[0];
        po[(size_t)(cha + 1) * V + v]     = c0[1];
        po[(size_t)cha * V + v + 8]       = c0[2];
        po[(size_t)(cha + 1) * V + v + 8] = c0[3];
        po[(size_t)chb * V + v]           = c1[0];
        po[(size_t)(chb + 1) * V + v]     = c1[1];
        po[(size_t)chb * V + v + 8]       = c1[2];
        po[(size_t)(chb + 1) * V + v + 8] = c1[3];
    }
}

// out[o][v] = bias[o] + sum_k sum_i T_k[i][v] W[k][i][o]
// T0=x, T1..T3 from g_T, T4 = 2*(p4 partial sum) - T2 reconstructed inline.
__global__ __launch_bounds__(128)
void cheb_combine(const float* __restrict__ x,
                  const float* __restrict__ Wt,
                  const float* __restrict__ bias,
                  float* __restrict__ out)
{
    __shared__ float Ws[KORD * CIN * COUT];
    __shared__ float bs[COUT];
    const int tid = threadIdx.x;
    for (int idx = tid; idx < KORD * CIN * COUT; idx += blockDim.x) Ws[idx] = Wt[idx];
    if (tid < COUT) bs[tid] = bias[tid];
    __syncthreads();

    const int v = blockIdx.x * blockDim.x + tid;

    float acc[COUT];
#pragma unroll
    for (int o = 0; o < COUT; o++) acc[o] = bs[o];

#pragma unroll
    for (int i = 0; i < CIN; i++) {
        const size_t iv = (size_t)i * V + v;
        float t2 = g_T[1][iv];
        float tv[KORD];
        tv[0] = x[iv];
        tv[1] = g_T[0][iv];
        tv[2] = t2;
        tv[3] = g_T[2][iv];
        tv[4] = 2.0f * (g_part[3][0][iv] + g_part[3][1][iv] + g_part[3][2][iv]) - t2;
#pragma unroll
        for (int k = 0; k < KORD; k++) {
            const float* wrow = &Ws[(k * CIN + i) * COUT];
#pragma unroll
            for (int o = 0; o < COUT; o++) acc[o] = fmaf(tv[k], wrow[o], acc[o]);
        }
    }
#pragma unroll
    for (int o = 0; o < COUT; o++) out[(size_t)o * V + v] = acc[o];
}

extern "C" void kernel_launch(void* const* d_in, const int* in_sizes, int n_in,
                              void* d_out, int out_size)
{
    const float* x  = (const float*)d_in[0];
    const float* L  = (const float*)d_in[1];
    const float* Wt = (const float*)d_in[2];
    const float* b  = (const float*)d_in[3];
    float* out = (float*)d_out;

    float* gT = nullptr;
    float* gP = nullptr;
    cudaGetSymbolAddress((void**)&gT, g_T);
    cudaGetSymbolAddress((void**)&gP, g_part);

    cudaFuncSetAttribute(cheb_pass_mma<0>, cudaFuncAttributeMaxDynamicSharedMemorySize, SMEM_DYN);
    cudaFuncSetAttribute(cheb_pass_mma<1>, cudaFuncAttributeMaxDynamicSharedMemorySize, SMEM_DYN);
    cudaFuncSetAttribute(cheb_pass_mma<2>, cudaFuncAttributeMaxDynamicSharedMemorySize, SMEM_DYN);

    const dim3 pgrid(96 * NKS);   // 288 CTAs = one full wave at 2 CTAs/SM
    const dim3 pblk(256);

    float* T1 = gT + 0 * CV;
    float* T2 = gT + 1 * CV;
    float* T3 = gT + 2 * CV;
    float* P1 = gP + 0 * (NKS * CV);
    float* P2 = gP + 1 * (NKS * CV);
    float* P3 = gP + 2 * (NKS * CV);
    float* P4 = gP + 3 * (NKS * CV);
    float* P1a = P1, *P1b = P1 + CV, *P1c = P1 + 2 * CV;
    float* P2a = P2, *P2b = P2 + CV, *P2c = P2 + 2 * CV;
    float* P3a = P3, *P3b = P3 + CV, *P3c = P3 + 2 * CV;

    // pass1: B = x                          -> P1
    cheb_pass_mma<0><<<pgrid, pblk, SMEM_DYN>>>(L, x, nullptr, nullptr, nullptr,
                                                nullptr, P1);
    // pass2: B = T1 = P1a+P1b+P1c (write T1) -> P2
    cheb_pass_mma<1><<<pgrid, pblk, SMEM_DYN>>>(L, P1a, P1b, P1c, nullptr,
                                                T1, P2);
    // pass3: B = T2 = 2*(sum P2) - x (write T2) -> P3
    cheb_pass_mma<2><<<pgrid, pblk, SMEM_DYN>>>(L, P2a, P2b, P2c, x,
                                                T2, P3);
    // pass4: B = T3 = 2*(sum P3) - T1 (write T3) -> P4
    cheb_pass_mma<2><<<pgrid, pblk, SMEM_DYN>>>(L, P3a, P3b, P3c, T1,
                                                T3, P4);
    // combine: T4 reconstructed from P4 inline
    cheb_combine<<<V / 128, 128>>>(x, Wt, b, out);
}

// round 10
// speedup vs baseline: 1.1314x; 1.1314x over previous
#include <cuda_runtime.h>
#include <cstdint>

#define V 12288
#define CIN 16
#define COUT 32
#define KORD 5
#define NKS 3               // k-slices per pass  -> 96*3 = 288 CTAs = 1 wave @2/SM
#define KSL (V / NKS)       // 4096
#define CHK 64              // u per chunk
#define NCHK (KSL / CHK)    // 64
#define CV (CIN * V)
#define RS 72               // smem row stride in bf16 elements
#define RSB (RS * 2)        // 144 bytes

// fp32 scratch: T1..T3 and per-kslice partials (pass-4 partials consumed by combine)
__device__ float g_T[3][CV];
__device__ float g_part[NKS][CV];

// per-stage smem byte offsets
#define AH_OFF 0
#define AL_OFF (128 * RSB)            // 18432
#define BH_OFF (2 * 128 * RSB)        // 36864
#define BL_OFF (BH_OFF + 16 * RSB)    // 39168
#define STAGE  (BL_OFF + 16 * RSB)    // 41472 per stage
#define SMEM_DYN (2 * STAGE)          // 82944

__device__ __forceinline__ uint32_t lds32(uint32_t a) {
    uint32_t v;
    asm volatile("ld.shared.b32 %0, [%1];" : "=r"(v) : "r"(a));
    return v;
}
__device__ __forceinline__ void sts64(uint32_t a, uint32_t w0, uint32_t w1) {
    asm volatile("st.shared.v2.b32 [%0], {%1,%2};" :: "r"(a), "r"(w0), "r"(w1) : "memory");
}

// split fp32 x4 -> bf16 hi (truncate) + bf16 lo (residual, RN); store 8B to each tile
__device__ __forceinline__ void split_sts(float4 f, uint32_t ah, uint32_t al) {
    uint32_t b0 = __float_as_uint(f.x), b1 = __float_as_uint(f.y);
    uint32_t b2 = __float_as_uint(f.z), b3 = __float_as_uint(f.w);
    uint32_t h0 = __byte_perm(b0, b1, 0x7632);
    uint32_t h1 = __byte_perm(b2, b3, 0x7632);
    float l0 = f.x - __uint_as_float(b0 & 0xFFFF0000u);
    float l1 = f.y - __uint_as_float(b1 & 0xFFFF0000u);
    float l2 = f.z - __uint_as_float(b2 & 0xFFFF0000u);
    float l3 = f.w - __uint_as_float(b3 & 0xFFFF0000u);
    uint32_t w0, w1;
    asm("cvt.rn.bf16x2.f32 %0, %1, %2;" : "=r"(w0) : "f"(l1), "f"(l0));
    asm("cvt.rn.bf16x2.f32 %0, %1, %2;" : "=r"(w1) : "f"(l3), "f"(l2));
    sts64(ah, h0, h1);
    sts64(al, w0, w1);
}

__device__ __forceinline__ void mma_bf16(float* c, uint32_t a0, uint32_t a1,
                                         uint32_t a2, uint32_t a3,
                                         uint32_t b0, uint32_t b1) {
    asm volatile("mma.sync.aligned.m16n8k16.row.col.f32.bf16.bf16.f32 "
                 "{%0,%1,%2,%3}, {%4,%5,%6,%7}, {%8,%9}, {%0,%1,%2,%3};"
                 : "+f"(c[0]), "+f"(c[1]), "+f"(c[2]), "+f"(c[3])
                 : "r"(a0), "r"(a1), "r"(a2), "r"(a3), "r"(b0), "r"(b1));
}

// ---------------- pass kernel (R8 engine, unchanged) ----------------
// g_part[ks][ch][v] = sum_{u in kslice} B[ch][u] * L[v][u]
__global__ __launch_bounds__(256, 2)
void cheb_pass_mma(const float* __restrict__ L, const float* __restrict__ B)
{
    extern __shared__ __align__(16) uint8_t smem[];
    const uint32_t sb = (uint32_t)__cvta_generic_to_shared(smem);

    const int t    = threadIdx.x;
    const int warp = t >> 5;
    const int lane = t & 31;
    const int g    = lane >> 2;
    const int tc   = lane & 3;
    const int vt   = blockIdx.x % 96;
    const int ks   = blockIdx.x / 96;
    const int ub   = ks * KSL;

    // Coalesced staging map: thread t, iter j -> row j*16 + (t>>4), col quad (t&15).
    const int rh = t >> 4;
    const int cq = t & 15;
    const float* Ag = L + (size_t)(vt * 128 + rh) * V + ub + cq * 4;
    const float* Bg = B + (size_t)rh * V + ub + cq * 4;
    const uint32_t st_off = (uint32_t)(rh * RSB + cq * 8);

    // fragment LDS offsets (relative to stage base)
    const int vw = warp * 16;
    const uint32_t a_frag = (uint32_t)((vw + g) * RSB + tc * 4);
    const uint32_t b_frag = (uint32_t)(g * RSB + tc * 4);

    float c0[4] = {0.f, 0.f, 0.f, 0.f};
    float c1[4] = {0.f, 0.f, 0.f, 0.f};

    float4 la[8];
    float4 lb;

    // prologue: load+stage chunk 0, load chunk 1 (B LDG issued with A LDGs)
    lb = __ldg((const float4*)(Bg));
#pragma unroll
    for (int j = 0; j < 8; j++)
        la[j] = __ldcs((const float4*)(Ag + (size_t)j * 16 * V));
    {
#pragma unroll
        for (int j = 0; j < 8; j++)
            split_sts(la[j], sb + AH_OFF + st_off + j * 2304,
                             sb + AL_OFF + st_off + j * 2304);
        split_sts(lb, sb + BH_OFF + st_off, sb + BL_OFF + st_off);
    }
    lb = __ldg((const float4*)(Bg + CHK));
#pragma unroll
    for (int j = 0; j < 8; j++)
        la[j] = __ldcs((const float4*)(Ag + (size_t)j * 16 * V + CHK));
    __syncthreads();

#pragma unroll 1
    for (int c = 0; c < NCHK; c++) {
        const uint32_t sbuf = sb + (uint32_t)(c & 1) * STAGE;

        // stage chunk c+1 into the other buffer
        if (c + 1 < NCHK) {
            const uint32_t so = sb + (uint32_t)((c + 1) & 1) * STAGE;
#pragma unroll
            for (int j = 0; j < 8; j++)
                split_sts(la[j], so + AH_OFF + st_off + j * 2304,
                                 so + AL_OFF + st_off + j * 2304);
            split_sts(lb, so + BH_OFF + st_off, so + BL_OFF + st_off);
        }
        // prefetch chunk c+2
        if (c + 2 < NCHK) {
            const int off = (c + 2) * CHK;
            lb = __ldg((const float4*)(Bg + off));
#pragma unroll
            for (int j = 0; j < 8; j++)
                la[j] = __ldcs((const float4*)(Ag + (size_t)j * 16 * V + off));
        }

        // compute chunk c: 4 k-steps x (2 n-tiles x 3 products)
#pragma unroll
        for (int s = 0; s < 4; s++) {
            const uint32_t ao = sbuf + a_frag + s * 32;
            const uint32_t bo = sbuf + b_frag + s * 32;
            uint32_t ah0 = lds32(ao + AH_OFF);
            uint32_t ah1 = lds32(ao + AH_OFF + 8 * RSB);
            uint32_t ah2 = lds32(ao + AH_OFF + 16);
            uint32_t ah3 = lds32(ao + AH_OFF + 8 * RSB + 16);
            uint32_t al0 = lds32(ao + AL_OFF);
            uint32_t al1 = lds32(ao + AL_OFF + 8 * RSB);
            uint32_t al2 = lds32(ao + AL_OFF + 16);
            uint32_t al3 = lds32(ao + AL_OFF + 8 * RSB + 16);

            uint32_t bh0 = lds32(bo + BH_OFF);
            uint32_t bh1 = lds32(bo + BH_OFF + 16);
            uint32_t bl0 = lds32(bo + BL_OFF);
            uint32_t bl1 = lds32(bo + BL_OFF + 16);
            mma_bf16(c0, ah0, ah1, ah2, ah3, bh0, bh1);
            mma_bf16(c0, ah0, ah1, ah2, ah3, bl0, bl1);
            mma_bf16(c0, al0, al1, al2, al3, bh0, bh1);

            uint32_t ch0 = lds32(bo + BH_OFF + 8 * RSB);
            uint32_t ch1 = lds32(bo + BH_OFF + 8 * RSB + 16);
            uint32_t cl0 = lds32(bo + BL_OFF + 8 * RSB);
            uint32_t cl1 = lds32(bo + BL_OFF + 8 * RSB + 16);
            mma_bf16(c1, ah0, ah1, ah2, ah3, ch0, ch1);
            mma_bf16(c1, ah0, ah1, ah2, ah3, cl0, cl1);
            mma_bf16(c1, al0, al1, al2, al3, ch0, ch1);
        }
        __syncthreads();
    }

    // epilogue: thread map rows g,g+8; cols 2tc,2tc+1
    {
        float* po = g_part[ks];
        const int v = vt * 128 + vw + g;
        const int cha = 2 * tc;
        const int chb = 8 + 2 * tc;
        po[(size_t)cha * V + v]           = c0[0];
        po[(size_t)(cha + 1) * V + v]     = c0[1];
        po[(size_t)cha * V + v + 8]       = c0[2];
        po[(size_t)(cha + 1) * V + v + 8] = c0[3];
        po[(size_t)chb * V + v]           = c1[0];
        po[(size_t)(chb + 1) * V + v]     = c1[1];
        po[(size_t)chb * V + v + 8]       = c1[2];
        po[(size_t)(chb + 1) * V + v + 8] = c1[3];
    }
}

// T_out = a * (sum of 3 partials) + b * prev
__global__ __launch_bounds__(256)
void cheb_reduce(const float* __restrict__ prev, float* __restrict__ Tout,
                 float a, float b)
{
    const int idx = blockIdx.x * 256 + threadIdx.x;
    float s = g_part[0][idx] + g_part[1][idx] + g_part[2][idx];
    float r = a * s;
    if (b != 0.0f) r += b * prev[idx];
    Tout[idx] = r;
}

// out[o][v] = bias[o] + sum_k sum_i T_k[i][v] W[k][i][o]
// T0=x, T1..T3 from g_T, T4 = 2*(sum g_part) - T2 reconstructed inline.
__global__ __launch_bounds__(128)
void cheb_combine(const float* __restrict__ x,
                  const float* __restrict__ Wt,
                  const float* __restrict__ bias,
                  float* __restrict__ out)
{
    __shared__ float Ws[KORD * CIN * COUT];
    __shared__ float bs[COUT];
    const int tid = threadIdx.x;
    for (int idx = tid; idx < KORD * CIN * COUT; idx += blockDim.x) Ws[idx] = Wt[idx];
    if (tid < COUT) bs[tid] = bias[tid];
    __syncthreads();

    const int v = blockIdx.x * blockDim.x + tid;

    float acc[COUT];
#pragma unroll
    for (int o = 0; o < COUT; o++) acc[o] = bs[o];

#pragma unroll
    for (int i = 0; i < CIN; i++) {
        const size_t iv = (size_t)i * V + v;
        float t2 = g_T[1][iv];
        float tv[KORD];
        tv[0] = x[iv];
        tv[1] = g_T[0][iv];
        tv[2] = t2;
        tv[3] = g_T[2][iv];
        tv[4] = 2.0f * (g_part[0][iv] + g_part[1][iv] + g_part[2][iv]) - t2;
#pragma unroll
        for (int k = 0; k < KORD; k++) {
            const float* wrow = &Ws[(k * CIN + i) * COUT];
#pragma unroll
            for (int o = 0; o < COUT; o++) acc[o] = fmaf(tv[k], wrow[o], acc[o]);
        }
    }
#pragma unroll
    for (int o = 0; o < COUT; o++) out[(size_t)o * V + v] = acc[o];
}

extern "C" void kernel_launch(void* const* d_in, const int* in_sizes, int n_in,
                              void* d_out, int out_size)
{
    const float* x  = (const float*)d_in[0];
    const float* L  = (const float*)d_in[1];
    const float* Wt = (const float*)d_in[2];
    const float* b  = (const float*)d_in[3];
    float* out = (float*)d_out;

    float* gT = nullptr;
    cudaGetSymbolAddress((void**)&gT, g_T);

    cudaFuncSetAttribute(cheb_pass_mma, cudaFuncAttributeMaxDynamicSharedMemorySize,
                         SMEM_DYN);

    const dim3 pgrid(96 * NKS);   // 288 CTAs = one full wave at 2 CTAs/SM
    const dim3 pblk(256);
    const dim3 rgrid(CV / 256);

    float* T1 = gT + 0 * CV;
    float* T2 = gT + 1 * CV;
    float* T3 = gT + 2 * CV;

    // T1 = x @ L^T
    cheb_pass_mma<<<pgrid, pblk, SMEM_DYN>>>(L, x);
    cheb_reduce<<<rgrid, 256>>>(x, T1, 1.0f, 0.0f);
    // T2 = 2 T1 @ L^T - x
    cheb_pass_mma<<<pgrid, pblk, SMEM_DYN>>>(L, T1);
    cheb_reduce<<<rgrid, 256>>>(x, T2, 2.0f, -1.0f);
    // T3 = 2 T2 @ L^T - T1
    cheb_pass_mma<<<pgrid, pblk, SMEM_DYN>>>(L, T2);
    cheb_reduce<<<rgrid, 256>>>(T1, T3, 2.0f, -1.0f);
    // pass 4 partials stay in g_part; combine reconstructs T4 = 2*sum - T2
    cheb_pass_mma<<<pgrid, pblk, SMEM_DYN>>>(L, T3);
    cheb_combine<<<V / 128, 128>>>(x, Wt, b, out);
}

// round 11
// speedup vs baseline: 1.1486x; 1.0152x over previous
#include <cuda_runtime.h>
#include <cstdint>

#define V 12288
#define CIN 16
#define COUT 32
#define KORD 5
#define NKS 3               // k-slices per pass  -> 96*3 = 288 CTAs = 1 wave @2/SM
#define KSL (V / NKS)       // 4096
#define CHK 64              // u per chunk
#define NCHK (KSL / CHK)    // 64
#define CV (CIN * V)
#define RS 72               // smem row stride in bf16 elements
#define RSB (RS * 2)        // 144 bytes
#define NCTA (96 * NKS)     // 288
#define NTHR (NCTA * 256)   // 73728

// fp32 scratch: T1..T3, per-kslice partials, grid-barrier counter
__device__ float g_T[3][CV];
__device__ float g_part[NKS][CV];
__device__ unsigned g_bar;   // monotonic across launches (288 incr per barrier)

// per-stage smem byte offsets
#define AH_OFF 0
#define AL_OFF (128 * RSB)            // 18432
#define BH_OFF (2 * 128 * RSB)        // 36864
#define BL_OFF (BH_OFF + 16 * RSB)    // 39168
#define STAGE  (BL_OFF + 16 * RSB)    // 41472 per stage
#define SMEM_DYN (2 * STAGE)          // 82944

__device__ __forceinline__ uint32_t lds32(uint32_t a) {
    uint32_t v;
    asm volatile("ld.shared.b32 %0, [%1];" : "=r"(v) : "r"(a));
    return v;
}
__device__ __forceinline__ void sts64(uint32_t a, uint32_t w0, uint32_t w1) {
    asm volatile("st.shared.v2.b32 [%0], {%1,%2};" :: "r"(a), "r"(w0), "r"(w1) : "memory");
}

// split fp32 x4 -> bf16 hi (truncate) + bf16 lo (residual, RN); store 8B to each tile
__device__ __forceinline__ void split_sts(float4 f, uint32_t ah, uint32_t al) {
    uint32_t b0 = __float_as_uint(f.x), b1 = __float_as_uint(f.y);
    uint32_t b2 = __float_as_uint(f.z), b3 = __float_as_uint(f.w);
    uint32_t h0 = __byte_perm(b0, b1, 0x7632);
    uint32_t h1 = __byte_perm(b2, b3, 0x7632);
    float l0 = f.x - __uint_as_float(b0 & 0xFFFF0000u);
    float l1 = f.y - __uint_as_float(b1 & 0xFFFF0000u);
    float l2 = f.z - __uint_as_float(b2 & 0xFFFF0000u);
    float l3 = f.w - __uint_as_float(b3 & 0xFFFF0000u);
    uint32_t w0, w1;
    asm("cvt.rn.bf16x2.f32 %0, %1, %2;" : "=r"(w0) : "f"(l1), "f"(l0));
    asm("cvt.rn.bf16x2.f32 %0, %1, %2;" : "=r"(w1) : "f"(l3), "f"(l2));
    sts64(ah, h0, h1);
    sts64(al, w0, w1);
}

__device__ __forceinline__ void mma_bf16(float* c, uint32_t a0, uint32_t a1,
                                         uint32_t a2, uint32_t a3,
                                         uint32_t b0, uint32_t b1) {
    asm volatile("mma.sync.aligned.m16n8k16.row.col.f32.bf16.bf16.f32 "
                 "{%0,%1,%2,%3}, {%4,%5,%6,%7}, {%8,%9}, {%0,%1,%2,%3};"
                 : "+f"(c[0]), "+f"(c[1]), "+f"(c[2]), "+f"(c[3])
                 : "r"(a0), "r"(a1), "r"(a2), "r"(a3), "r"(b0), "r"(b1));
}

// software grid barrier: all 288 CTAs co-resident (one wave). Monotonic counter;
// target = ceil(counter to multiple of 288) -> safe across graph replays.
__device__ __forceinline__ void grid_barrier(int tid) {
    __syncthreads();
    if (tid == 0) {
        __threadfence();
        unsigned old = atomicAdd(&g_bar, 1u) + 1u;
        unsigned target = ((old + (NCTA - 1u)) / NCTA) * NCTA;
        for (;;) {
            unsigned cur;
            asm volatile("ld.global.acquire.gpu.u32 %0, [%1];"
                         : "=r"(cur) : "l"(&g_bar));
            if (cur >= target) break;
            __nanosleep(64);
        }
    }
    __syncthreads();
}

// ---------------- pass body (R10 engine, verbatim) ----------------
__device__ __forceinline__ void pass_body(
    const float* __restrict__ L, const float* __restrict__ B,
    uint32_t sb, int t, int warp, int lane, int vt, int ks)
{
    const int g    = lane >> 2;
    const int tc   = lane & 3;
    const int ub   = ks * KSL;

    const int rh = t >> 4;
    const int cq = t & 15;
    const float* Ag = L + (size_t)(vt * 128 + rh) * V + ub + cq * 4;
    const float* Bg = B + (size_t)rh * V + ub + cq * 4;
    const uint32_t st_off = (uint32_t)(rh * RSB + cq * 8);

    const int vw = warp * 16;
    const uint32_t a_frag = (uint32_t)((vw + g) * RSB + tc * 4);
    const uint32_t b_frag = (uint32_t)(g * RSB + tc * 4);

    float c0[4] = {0.f, 0.f, 0.f, 0.f};
    float c1[4] = {0.f, 0.f, 0.f, 0.f};

    float4 la[8];
    float4 lb;

    lb = __ldg((const float4*)(Bg));
#pragma unroll
    for (int j = 0; j < 8; j++)
        la[j] = __ldcs((const float4*)(Ag + (size_t)j * 16 * V));
    {
#pragma unroll
        for (int j = 0; j < 8; j++)
            split_sts(la[j], sb + AH_OFF + st_off + j * 2304,
                             sb + AL_OFF + st_off + j * 2304);
        split_sts(lb, sb + BH_OFF + st_off, sb + BL_OFF + st_off);
    }
    lb = __ldg((const float4*)(Bg + CHK));
#pragma unroll
    for (int j = 0; j < 8; j++)
        la[j] = __ldcs((const float4*)(Ag + (size_t)j * 16 * V + CHK));
    __syncthreads();

#pragma unroll 1
    for (int c = 0; c < NCHK; c++) {
        const uint32_t sbuf = sb + (uint32_t)(c & 1) * STAGE;

        if (c + 1 < NCHK) {
            const uint32_t so = sb + (uint32_t)((c + 1) & 1) * STAGE;
#pragma unroll
            for (int j = 0; j < 8; j++)
                split_sts(la[j], so + AH_OFF + st_off + j * 2304,
                                 so + AL_OFF + st_off + j * 2304);
            split_sts(lb, so + BH_OFF + st_off, so + BL_OFF + st_off);
        }
        if (c + 2 < NCHK) {
            const int off = (c + 2) * CHK;
            lb = __ldg((const float4*)(Bg + off));
#pragma unroll
            for (int j = 0; j < 8; j++)
                la[j] = __ldcs((const float4*)(Ag + (size_t)j * 16 * V + off));
        }

#pragma unroll
        for (int s = 0; s < 4; s++) {
            const uint32_t ao = sbuf + a_frag + s * 32;
            const uint32_t bo = sbuf + b_frag + s * 32;
            uint32_t ah0 = lds32(ao + AH_OFF);
            uint32_t ah1 = lds32(ao + AH_OFF + 8 * RSB);
            uint32_t ah2 = lds32(ao + AH_OFF + 16);
            uint32_t ah3 = lds32(ao + AH_OFF + 8 * RSB + 16);
            uint32_t al0 = lds32(ao + AL_OFF);
            uint32_t al1 = lds32(ao + AL_OFF + 8 * RSB);
            uint32_t al2 = lds32(ao + AL_OFF + 16);
            uint32_t al3 = lds32(ao + AL_OFF + 8 * RSB + 16);

            uint32_t bh0 = lds32(bo + BH_OFF);
            uint32_t bh1 = lds32(bo + BH_OFF + 16);
            uint32_t bl0 = lds32(bo + BL_OFF);
            uint32_t bl1 = lds32(bo + BL_OFF + 16);
            mma_bf16(c0, ah0, ah1, ah2, ah3, bh0, bh1);
            mma_bf16(c0, ah0, ah1, ah2, ah3, bl0, bl1);
            mma_bf16(c0, al0, al1, al2, al3, bh0, bh1);

            uint32_t ch0 = lds32(bo + BH_OFF + 8 * RSB);
            uint32_t ch1 = lds32(bo + BH_OFF + 8 * RSB + 16);
            uint32_t cl0 = lds32(bo + BL_OFF + 8 * RSB);
            uint32_t cl1 = lds32(bo + BL_OFF + 8 * RSB + 16);
            mma_bf16(c1, ah0, ah1, ah2, ah3, ch0, ch1);
            mma_bf16(c1, ah0, ah1, ah2, ah3, cl0, cl1);
            mma_bf16(c1, al0, al1, al2, al3, ch0, ch1);
        }
        __syncthreads();
    }

    // epilogue: thread map rows g,g+8; cols 2tc,2tc+1
    {
        float* po = g_part[ks];
        const int v = vt * 128 + vw + g;
        const int cha = 2 * tc;
        const int chb = 8 + 2 * tc;
        po[(size_t)cha * V + v]           = c0[0];
        po[(size_t)(cha + 1) * V + v]     = c0[1];
        po[(size_t)cha * V + v + 8]       = c0[2];
        po[(size_t)(cha + 1) * V + v + 8] = c0[3];
        po[(size_t)chb * V + v]           = c1[0];
        po[(size_t)(chb + 1) * V + v]     = c1[1];
        po[(size_t)chb * V + v + 8]       = c1[2];
        po[(size_t)(chb + 1) * V + v + 8] = c1[3];
    }
}

// ---------------- single persistent kernel ----------------
__global__ __launch_bounds__(256, 2)
void cheb_all(const float* __restrict__ x,
              const float* __restrict__ L,
              const float* __restrict__ Wt,
              const float* __restrict__ bias,
              float* __restrict__ out)
{
    extern __shared__ __align__(16) uint8_t smem[];
    const uint32_t sb = (uint32_t)__cvta_generic_to_shared(smem);

    const int t    = threadIdx.x;
    const int warp = t >> 5;
    const int lane = t & 31;
    const int vt   = blockIdx.x % 96;
    const int ks   = blockIdx.x / 96;
    const int gi   = blockIdx.x * 256 + t;   // 0..73727

    const float* Bptr = x;

#pragma unroll 1
    for (int pass = 0; pass < 4; pass++) {
        pass_body(L, Bptr, sb, t, warp, lane, vt, ks);
        grid_barrier(t);                 // partials of this pass visible

        if (pass < 3) {
            // reduce: T_pass = a*(p0+p1+p2) + b*prev  (float4 granularity)
            if (gi < CV / 4) {
                const float4 s0 = ((const float4*)g_part[0])[gi];
                const float4 s1 = ((const float4*)g_part[1])[gi];
                const float4 s2 = ((const float4*)g_part[2])[gi];
                float4 r;
                r.x = s0.x + s1.x + s2.x;
                r.y = s0.y + s1.y + s2.y;
                r.z = s0.z + s1.z + s2.z;
                r.w = s0.w + s1.w + s2.w;
                if (pass > 0) {
                    const float* prev = (pass == 1) ? x : g_T[0];
                    const float4 pv = ((const float4*)prev)[gi];
                    r.x = 2.0f * r.x - pv.x;
                    r.y = 2.0f * r.y - pv.y;
                    r.z = 2.0f * r.z - pv.z;
                    r.w = 2.0f * r.w - pv.w;
                }
                ((float4*)g_T[pass])[gi] = r;
            }
            grid_barrier(t);             // T_pass visible before next pass reads it
            Bptr = g_T[pass];
        }
    }

    // ---------------- combine (first 48 CTAs; smem reused for W) ----------------
    if (blockIdx.x < V / 256) {
        float* Wsh = (float*)smem;                 // 2560 floats
        float* bsh = Wsh + KORD * CIN * COUT;
        for (int idx = t; idx < KORD * CIN * COUT; idx += 256) Wsh[idx] = Wt[idx];
        if (t < COUT) bsh[t] = bias[t];
        __syncthreads();

        const int v = blockIdx.x * 256 + t;        // < 12288

        float acc[COUT];
#pragma unroll
        for (int o = 0; o < COUT; o++) acc[o] = bsh[o];

#pragma unroll
        for (int i = 0; i < CIN; i++) {
            const size_t iv = (size_t)i * V + v;
            float t2 = g_T[1][iv];
            float tv[KORD];
            tv[0] = x[iv];
            tv[1] = g_T[0][iv];
            tv[2] = t2;
            tv[3] = g_T[2][iv];
            tv[4] = 2.0f * (g_part[0][iv] + g_part[1][iv] + g_part[2][iv]) - t2;
#pragma unroll
            for (int k = 0; k < KORD; k++) {
                const float* wrow = &Wsh[(k * CIN + i) * COUT];
#pragma unroll
                for (int o = 0; o < COUT; o++) acc[o] = fmaf(tv[k], wrow[o], acc[o]);
            }
        }
#pragma unroll
        for (int o = 0; o < COUT; o++) out[(size_t)o * V + v] = acc[o];
    }
}

extern "C" void kernel_launch(void* const* d_in, const int* in_sizes, int n_in,
                              void* d_out, int out_size)
{
    const float* x  = (const float*)d_in[0];
    const float* L  = (const float*)d_in[1];
    const float* Wt = (const float*)d_in[2];
    const float* b  = (const float*)d_in[3];
    float* out = (float*)d_out;

    cudaFuncSetAttribute(cheb_all, cudaFuncAttributeMaxDynamicSharedMemorySize,
                         SMEM_DYN);

    cheb_all<<<NCTA, 256, SMEM_DYN>>>(x, L, Wt, b, out);
}